// round 5
// baseline (speedup 1.0000x reference)
#include <cuda_runtime.h>
#include <cuda_bf16.h>

#define EMB 64
#define NV 16                 // float4 per embedding row
#define N_USER_MAX 100000
#define N_ITEM_MAX 50000
#define NMAX (N_USER_MAX + N_ITEM_MAX)

// Scratch state (allocation-free rule: __device__ globals)
__device__ float g_ego[(size_t)NMAX * EMB];        // 38.4 MB
__device__ float g_side[(size_t)NMAX * EMB];       // 38.4 MB
__device__ float g_alle[(size_t)NMAX * EMB * 4];   // 153.6 MB  (layer-concat output)
__device__ int   g_idx64;                          // 1 if batch index arrays are int64

// ---------------------------------------------------------------------------
// Init: ego = concat(user_emb, item_emb); all_e[:, 0:64] = ego; side = 0
// ---------------------------------------------------------------------------
__global__ void init_kernel(const float4* __restrict__ ue,
                            const float4* __restrict__ ie,
                            int n_user, int n) {
    long long gid = (long long)blockIdx.x * blockDim.x + threadIdx.x;
    long long total = (long long)n * NV;
    if (gid >= total) return;
    int node = (int)(gid / NV);
    int c    = (int)(gid % NV);
    float4 v = (node < n_user) ? ue[(long long)node * NV + c]
                               : ie[(long long)(node - n_user) * NV + c];
    ((float4*)g_ego)[gid] = v;
    ((float4*)g_alle)[(long long)node * (NV * 4) + c] = v;           // cols 0..63
    ((float4*)g_side)[gid] = make_float4(0.f, 0.f, 0.f, 0.f);
}

// ---------------------------------------------------------------------------
// Scatter: side[dst] += ego[src] * w   (16 threads per edge, float4 RED)
// ---------------------------------------------------------------------------
__device__ __forceinline__ void atomic_add_f4(float4* p, float4 v) {
#if __CUDA_ARCH__ >= 900
    atomicAdd(p, v);
#else
    atomicAdd(&p->x, v.x); atomicAdd(&p->y, v.y);
    atomicAdd(&p->z, v.z); atomicAdd(&p->w, v.w);
#endif
}

__global__ __launch_bounds__(256) void scatter_kernel(
                               const int* __restrict__ src,
                               const int* __restrict__ dst,
                               const float* __restrict__ w,
                               long long nwork) {
    long long gid = (long long)blockIdx.x * blockDim.x + threadIdx.x;
    if (gid >= nwork) return;
    int e = (int)(gid >> 4);
    int c = (int)(gid & 15);
    int s = __ldg(src + e);
    int d = __ldg(dst + e);
    float wt = __ldg(w + e);
    float4 v = ((const float4*)g_ego)[(long long)s * NV + c];
    v.x *= wt; v.y *= wt; v.z *= wt; v.w *= wt;
    atomic_add_f4(((float4*)g_side) + (long long)d * NV + c, v);
}

// ---------------------------------------------------------------------------
// Transform: per node  e = leaky(side@Wg + bg + (ego*side)@Wb + bb, 0.2)
//            ego <- e ;  all_e[:, koff:koff+64] <- e / max(||e||, 1e-12)
//            side <- 0 (ready for next layer)
// 64 threads per node, 4 nodes per 256-thread block, grid-stride.
// ---------------------------------------------------------------------------
__global__ __launch_bounds__(256) void transform_kernel(
        const float* __restrict__ Wg, const float* __restrict__ bg,
        const float* __restrict__ Wb, const float* __restrict__ bb,
        int n, int koff) {
    __shared__ float sWg[EMB * EMB];
    __shared__ float sWb[EMB * EMB];
    __shared__ float sbg[EMB], sbb[EMB];
    __shared__ float sxs[4][EMB];   // side row per group
    __shared__ float sxb[4][EMB];   // ego*side row per group
    __shared__ float sss[4][2];     // partial sum-of-squares per group/warp

    int tid = threadIdx.x;
    for (int i = tid; i < EMB * EMB; i += blockDim.x) {
        sWg[i] = Wg[i];
        sWb[i] = Wb[i];
    }
    if (tid < EMB) { sbg[tid] = bg[tid]; sbb[tid] = bb[tid]; }
    __syncthreads();

    int g    = tid >> 6;          // node group 0..3
    int j    = tid & 63;          // output column
    int wing = (tid >> 5) & 1;    // warp within group
    int lane = tid & 31;

    long long n_iters = ((long long)n + 3) / 4;
    for (long long nb = blockIdx.x; nb < n_iters; nb += gridDim.x) {
        long long node = nb * 4 + g;
        bool valid = node < n;
        float sd = 0.f, eg = 0.f;
        if (valid) {
            sd = g_side[node * EMB + j];
            eg = g_ego [node * EMB + j];
            g_side[node * EMB + j] = 0.f;   // reset for next layer
        }
        sxs[g][j] = sd;
        sxb[g][j] = eg * sd;
        __syncthreads();

        float a1 = sbg[j], a2 = sbb[j];
#pragma unroll
        for (int i = 0; i < EMB; i++) {
            a1 = fmaf(sxs[g][i], sWg[i * EMB + j], a1);
            a2 = fmaf(sxb[g][i], sWb[i * EMB + j], a2);
        }
        float e = a1 + a2;
        e = (e >= 0.f) ? e : 0.2f * e;

        float ss = e * e;
#pragma unroll
        for (int o = 16; o > 0; o >>= 1) ss += __shfl_xor_sync(0xffffffffu, ss, o);
        if (lane == 0) sss[g][wing] = ss;
        __syncthreads();
        float inv = 1.f / fmaxf(sqrtf(sss[g][0] + sss[g][1]), 1e-12f);

        if (valid) {
            g_ego [node * EMB + j] = e;
            g_alle[node * (EMB * 4) + koff + j] = e * inv;
        }
        __syncthreads();   // protect sxs/sss before next iteration
    }
}

// ---------------------------------------------------------------------------
// Detect int64 vs int32 batch indices. If data is int64 (LE), every odd
// 32-bit word (high half) is 0 (indices < 2^31). 4096 random int32 indices
// all being 0 in their odd words is impossible, so OR distinguishes.
// ---------------------------------------------------------------------------
__global__ void detect_kernel(const int* __restrict__ users, int nb) {
    __shared__ int s;
    if (threadIdx.x == 0) s = 0;
    __syncthreads();
    int acc = 0;
    for (int i = threadIdx.x; i < nb / 2; i += blockDim.x)
        acc |= users[2 * i + 1];
    atomicOr(&s, acc);
    __syncthreads();
    if (threadIdx.x == 0) g_idx64 = (s == 0) ? 1 : 0;
}

// ---------------------------------------------------------------------------
// Gather final outputs: [u_g ; i_g[pos] ; i_g[neg]], each (nb, 256) fp32
// ---------------------------------------------------------------------------
__global__ void gather_kernel(const void* __restrict__ users,
                              const void* __restrict__ pos,
                              const void* __restrict__ neg,
                              float* __restrict__ out,
                              int n_user, int nb) {
    int flag = g_idx64;
    long long gid = (long long)blockIdx.x * blockDim.x + threadIdx.x;
    long long total = 3LL * nb * 64;        // 64 float4 per 256-col row
    if (gid >= total) return;
    int c = (int)(gid & 63);
    long long r = gid >> 6;
    int which = (int)(r / nb);
    int b     = (int)(r % nb);
    const void* p = (which == 0) ? users : (which == 1) ? pos : neg;
    long long idx = flag ? ((const long long*)p)[b]
                         : (long long)((const int*)p)[b];
    long long row = (which == 0) ? idx : ((long long)n_user + idx);
    ((float4*)out)[gid] = ((const float4*)g_alle)[row * 64 + c];
}

// ---------------------------------------------------------------------------
extern "C" void kernel_launch(void* const* d_in, const int* in_sizes, int n_in,
                              void* d_out, int out_size) {
    const float* user_emb = (const float*)d_in[0];
    const float* item_emb = (const float*)d_in[1];
    const float* W_gc     = (const float*)d_in[2];
    const float* b_gc     = (const float*)d_in[3];
    const float* W_bi     = (const float*)d_in[4];
    const float* b_bi     = (const float*)d_in[5];
    const float* edge_w   = (const float*)d_in[6];
    const int*   edge_src = (const int*)d_in[7];
    const int*   edge_dst = (const int*)d_in[8];
    const void*  users    = d_in[9];
    const void*  pos      = d_in[10];
    const void*  neg      = d_in[11];

    int n_user  = in_sizes[0] / EMB;
    int n_item  = in_sizes[1] / EMB;
    int n       = n_user + n_item;
    int n_edges = in_sizes[6];
    int layers  = in_sizes[2] / (EMB * EMB);
    int nb      = in_sizes[9];

    // Init
    {
        long long total = (long long)n * NV;
        int blocks = (int)((total + 255) / 256);
        init_kernel<<<blocks, 256>>>((const float4*)user_emb,
                                     (const float4*)item_emb, n_user, n);
    }

    // Layers
    for (int k = 0; k < layers; k++) {
        long long nwork = (long long)n_edges * 16;
        int sblocks = (int)((nwork + 255) / 256);
        scatter_kernel<<<sblocks, 256>>>(edge_src, edge_dst, edge_w, nwork);

        transform_kernel<<<1480, 256>>>(W_gc + (long long)k * EMB * EMB,
                                        b_gc + (long long)k * EMB,
                                        W_bi + (long long)k * EMB * EMB,
                                        b_bi + (long long)k * EMB,
                                        n, EMB * (k + 1));
    }

    // Output gathers
    detect_kernel<<<1, 256>>>((const int*)users, nb);
    {
        long long total = 3LL * nb * 64;
        int blocks = (int)((total + 255) / 256);
        gather_kernel<<<blocks, 256>>>(users, pos, neg, (float*)d_out,
                                       n_user, nb);
    }
}

// round 6
// speedup vs baseline: 1.4080x; 1.4080x over previous
#include <cuda_runtime.h>
#include <cuda_bf16.h>

#define EMB 64
#define N_USER_MAX 100000
#define N_ITEM_MAX 50000
#define NMAX (N_USER_MAX + N_ITEM_MAX)
#define EMAX 4200000          // max directed edges (2*N_INTER + slack)

// -------------------- device scratch (allocation-free rule) ----------------
__device__ float g_ego [(size_t)NMAX * EMB];         // ping
__device__ float g_ego2[(size_t)NMAX * EMB];         // pong
__device__ float g_alle[(size_t)NMAX * EMB * 4];     // layer-concat output
__device__ int   g_deg [NMAX];
__device__ int   g_off [NMAX];
__device__ int   g_cur [NMAX];
__device__ int   g_bsum[128];
__device__ int   g_csr_src[EMAX];
__device__ float g_csr_w  [EMAX];
__device__ int   g_idx64;

// packed fp32x2 FMA (Blackwell): d = a*b + d  (elementwise on 2 floats)
__device__ __forceinline__ unsigned long long pk2(float lo, float hi) {
    unsigned long long r;
    asm("mov.b64 %0, {%1,%2};" : "=l"(r) : "f"(lo), "f"(hi));
    return r;
}
__device__ __forceinline__ void fma2(unsigned long long& d,
                                     unsigned long long a,
                                     unsigned long long b) {
    asm("fma.rn.f32x2 %0, %1, %2, %3;" : "=l"(d) : "l"(a), "l"(b), "l"(d));
}
__device__ __forceinline__ float2 upk2(unsigned long long v) {
    float2 r;
    asm("mov.b64 {%0,%1}, %2;" : "=f"(r.x), "=f"(r.y) : "l"(v));
    return r;
}

// ---------------------------------------------------------------------------
// Init: ego = concat(user_emb, item_emb); all_e[:, 0:64] = ego
// ---------------------------------------------------------------------------
__global__ void init_kernel(const float4* __restrict__ ue,
                            const float4* __restrict__ ie,
                            int n_user, int n) {
    long long gid = (long long)blockIdx.x * blockDim.x + threadIdx.x;
    long long total = (long long)n * 16;
    if (gid >= total) return;
    int node = (int)(gid >> 4);
    int c    = (int)(gid & 15);
    float4 v = (node < n_user) ? ue[(long long)node * 16 + c]
                               : ie[(long long)(node - n_user) * 16 + c];
    ((float4*)g_ego)[gid] = v;
    ((float4*)g_alle)[(long long)node * 64 + c] = v;   // cols 0..63
}

// -------------------------- CSR build --------------------------------------
__global__ void zero_kernel(int n) {
    int i = blockIdx.x * blockDim.x + threadIdx.x;
    if (i < n) { g_deg[i] = 0; g_cur[i] = 0; }
}

__global__ void hist_kernel(const int* __restrict__ dst, int ne) {
    int e = blockIdx.x * blockDim.x + threadIdx.x;
    if (e < ne) atomicAdd(&g_deg[dst[e]], 1);
}

// scan1: per-2048-chunk exclusive scan of g_deg -> g_off, chunk totals -> g_bsum
__global__ __launch_bounds__(256) void scan1_kernel(int n) {
    __shared__ int sth[256];
    int tid = threadIdx.x;
    int base = blockIdx.x * 2048 + tid * 8;
    int v[8]; int sum = 0;
#pragma unroll
    for (int j = 0; j < 8; j++) {
        v[j] = (base + j < n) ? g_deg[base + j] : 0;
        sum += v[j];
    }
    sth[tid] = sum;
    __syncthreads();
    for (int o = 1; o < 256; o <<= 1) {
        int t = (tid >= o) ? sth[tid - o] : 0;
        __syncthreads();
        sth[tid] += t;
        __syncthreads();
    }
    int run = (tid > 0) ? sth[tid - 1] : 0;   // exclusive prefix for thread
#pragma unroll
    for (int j = 0; j < 8; j++) {
        if (base + j < n) g_off[base + j] = run;
        run += v[j];
    }
    if (tid == 255) g_bsum[blockIdx.x] = sth[255];
}

// scan2: exclusive scan of g_bsum (nb <= 128) in one block
__global__ void scan2_kernel(int nb) {
    __shared__ int s[128];
    int tid = threadIdx.x;
    s[tid] = (tid < nb) ? g_bsum[tid] : 0;
    __syncthreads();
    for (int o = 1; o < 128; o <<= 1) {
        int t = (tid >= o) ? s[tid - o] : 0;
        __syncthreads();
        s[tid] += t;
        __syncthreads();
    }
    if (tid < nb) g_bsum[tid] = (tid > 0) ? s[tid - 1] : 0;
}

__global__ void scan3_kernel(int n) {
    int i = blockIdx.x * blockDim.x + threadIdx.x;
    if (i < n) g_off[i] += g_bsum[i >> 11];
}

__global__ void fill_kernel(const int* __restrict__ src,
                            const int* __restrict__ dst,
                            const float* __restrict__ w, int ne) {
    int e = blockIdx.x * blockDim.x + threadIdx.x;
    if (e >= ne) return;
    int d = dst[e];
    int pos = g_off[d] + atomicAdd(&g_cur[d], 1);
    if (pos < EMAX) {
        g_csr_src[pos] = src[e];
        g_csr_w[pos]   = w[e];
    }
}

// ---------------------------------------------------------------------------
// Fused layer: warp-per-node pull aggregation + dual GEMV + leaky + norm
// ---------------------------------------------------------------------------
__global__ __launch_bounds__(256) void layer_kernel(
        const float* __restrict__ Wg, const float* __restrict__ bg,
        const float* __restrict__ Wb, const float* __restrict__ bb,
        const float* __restrict__ ego_in, float* __restrict__ ego_out,
        int n, int koff) {
    __shared__ float sWg[EMB * EMB];
    __shared__ float sWb[EMB * EMB];
    __shared__ float sbg[EMB], sbb[EMB];

    int tid = threadIdx.x;
    for (int i = tid; i < EMB * EMB; i += 256) { sWg[i] = Wg[i]; sWb[i] = Wb[i]; }
    if (tid < EMB) { sbg[tid] = bg[tid]; sbb[tid] = bb[tid]; }
    __syncthreads();

    int warp = tid >> 5;
    int lane = tid & 31;
    const unsigned FULL = 0xFFFFFFFFu;
    const float2* ego2 = (const float2*)ego_in;

    for (int node = blockIdx.x * 8 + warp; node < n; node += gridDim.x * 8) {
        int beg = g_off[node];
        int cnt_all = g_deg[node];

        float2 a0 = {0.f, 0.f}, a1v = {0.f, 0.f};
        float2 a2v = {0.f, 0.f}, a3v = {0.f, 0.f};
        for (int base = 0; base < cnt_all; base += 32) {
            int s = 0; float wt = 0.f;
            if (base + lane < cnt_all) {
                int e = beg + base + lane;
                s  = g_csr_src[e];
                wt = g_csr_w[e];
            }
            int cnt = min(32, cnt_all - base);
            int k = 0;
            for (; k + 4 <= cnt; k += 4) {
                int   s0 = __shfl_sync(FULL, s,  k);
                int   s1 = __shfl_sync(FULL, s,  k + 1);
                int   s2 = __shfl_sync(FULL, s,  k + 2);
                int   s3 = __shfl_sync(FULL, s,  k + 3);
                float w0 = __shfl_sync(FULL, wt, k);
                float w1 = __shfl_sync(FULL, wt, k + 1);
                float w2 = __shfl_sync(FULL, wt, k + 2);
                float w3 = __shfl_sync(FULL, wt, k + 3);
                float2 v0 = ego2[s0 * 32 + lane];
                float2 v1 = ego2[s1 * 32 + lane];
                float2 v2 = ego2[s2 * 32 + lane];
                float2 v3 = ego2[s3 * 32 + lane];
                a0.x  = fmaf(w0, v0.x, a0.x);  a0.y  = fmaf(w0, v0.y, a0.y);
                a1v.x = fmaf(w1, v1.x, a1v.x); a1v.y = fmaf(w1, v1.y, a1v.y);
                a2v.x = fmaf(w2, v2.x, a2v.x); a2v.y = fmaf(w2, v2.y, a2v.y);
                a3v.x = fmaf(w3, v3.x, a3v.x); a3v.y = fmaf(w3, v3.y, a3v.y);
            }
            for (; k < cnt; k++) {
                int   ss = __shfl_sync(FULL, s,  k);
                float ww = __shfl_sync(FULL, wt, k);
                float2 v = ego2[ss * 32 + lane];
                a0.x = fmaf(ww, v.x, a0.x); a0.y = fmaf(ww, v.y, a0.y);
            }
        }
        float2 side;
        side.x = (a0.x + a1v.x) + (a2v.x + a3v.x);
        side.y = (a0.y + a1v.y) + (a2v.y + a3v.y);

        float2 eg = ego2[node * 32 + lane];
        float2 xb = make_float2(eg.x * side.x, eg.y * side.y);

        // Dual GEMV: out[j] = bias[j] + sum_i x[i] * W[i*64+j]
        unsigned long long accg = pk2(sbg[2 * lane], sbg[2 * lane + 1]);
        unsigned long long accb = pk2(sbb[2 * lane], sbb[2 * lane + 1]);
#pragma unroll 4
        for (int p = 0; p < 32; p++) {
            float xs0 = __shfl_sync(FULL, side.x, p);
            float xs1 = __shfl_sync(FULL, side.y, p);
            float xb0 = __shfl_sync(FULL, xb.x,  p);
            float xb1 = __shfl_sync(FULL, xb.y,  p);
            float2 g0 = *(const float2*)&sWg[(2 * p)     * EMB + 2 * lane];
            float2 g1 = *(const float2*)&sWg[(2 * p + 1) * EMB + 2 * lane];
            float2 b0 = *(const float2*)&sWb[(2 * p)     * EMB + 2 * lane];
            float2 b1 = *(const float2*)&sWb[(2 * p + 1) * EMB + 2 * lane];
            fma2(accg, pk2(xs0, xs0), pk2(g0.x, g0.y));
            fma2(accg, pk2(xs1, xs1), pk2(g1.x, g1.y));
            fma2(accb, pk2(xb0, xb0), pk2(b0.x, b0.y));
            fma2(accb, pk2(xb1, xb1), pk2(b1.x, b1.y));
        }
        float2 rg = upk2(accg);
        float2 rb = upk2(accb);
        float2 e2;
        e2.x = rg.x + rb.x;
        e2.y = rg.y + rb.y;
        e2.x = (e2.x >= 0.f) ? e2.x : 0.2f * e2.x;
        e2.y = (e2.y >= 0.f) ? e2.y : 0.2f * e2.y;

        float ssq = e2.x * e2.x + e2.y * e2.y;
#pragma unroll
        for (int o = 16; o > 0; o >>= 1) ssq += __shfl_xor_sync(FULL, ssq, o);
        float inv = 1.f / fmaxf(sqrtf(ssq), 1e-12f);

        ((float2*)ego_out)[node * 32 + lane] = e2;
        *(float2*)&g_alle[(long long)node * 256 + koff + 2 * lane] =
            make_float2(e2.x * inv, e2.y * inv);
    }
}

// ---------------------------------------------------------------------------
// int64 vs int32 index detection (odd 32-bit words all zero => int64 LE)
// ---------------------------------------------------------------------------
__global__ void detect_kernel(const int* __restrict__ users, int nb) {
    __shared__ int s;
    if (threadIdx.x == 0) s = 0;
    __syncthreads();
    int acc = 0;
    for (int i = threadIdx.x; i < nb / 2; i += blockDim.x)
        acc |= users[2 * i + 1];
    atomicOr(&s, acc);
    __syncthreads();
    if (threadIdx.x == 0) g_idx64 = (s == 0) ? 1 : 0;
}

// ---------------------------------------------------------------------------
// Gather final outputs: [u_g ; i_g[pos] ; i_g[neg]], each (nb, 256) fp32
// ---------------------------------------------------------------------------
__global__ void gather_kernel(const void* __restrict__ users,
                              const void* __restrict__ pos,
                              const void* __restrict__ neg,
                              float* __restrict__ out,
                              int n_user, int nb) {
    int flag = g_idx64;
    long long gid = (long long)blockIdx.x * blockDim.x + threadIdx.x;
    long long total = 3LL * nb * 64;
    if (gid >= total) return;
    int c = (int)(gid & 63);
    long long r = gid >> 6;
    int which = (int)(r / nb);
    int b     = (int)(r % nb);
    const void* p = (which == 0) ? users : (which == 1) ? pos : neg;
    long long idx = flag ? ((const long long*)p)[b]
                         : (long long)((const int*)p)[b];
    long long row = (which == 0) ? idx : ((long long)n_user + idx);
    ((float4*)out)[gid] = ((const float4*)g_alle)[row * 64 + c];
}

// ---------------------------------------------------------------------------
extern "C" void kernel_launch(void* const* d_in, const int* in_sizes, int n_in,
                              void* d_out, int out_size) {
    const float* user_emb = (const float*)d_in[0];
    const float* item_emb = (const float*)d_in[1];
    const float* W_gc     = (const float*)d_in[2];
    const float* b_gc     = (const float*)d_in[3];
    const float* W_bi     = (const float*)d_in[4];
    const float* b_bi     = (const float*)d_in[5];
    const float* edge_w   = (const float*)d_in[6];
    const int*   edge_src = (const int*)d_in[7];
    const int*   edge_dst = (const int*)d_in[8];
    const void*  users    = d_in[9];
    const void*  pos      = d_in[10];
    const void*  neg      = d_in[11];

    int n_user  = in_sizes[0] / EMB;
    int n_item  = in_sizes[1] / EMB;
    int n       = n_user + n_item;
    int n_edges = in_sizes[6];
    int layers  = in_sizes[2] / (EMB * EMB);
    int nb      = in_sizes[9];

    // ego init + alle cols 0..63
    {
        long long total = (long long)n * 16;
        init_kernel<<<(int)((total + 255) / 256), 256>>>(
            (const float4*)user_emb, (const float4*)item_emb, n_user, n);
    }

    // CSR build (by dst)
    zero_kernel<<<(n + 255) / 256, 256>>>(n);
    hist_kernel<<<(n_edges + 255) / 256, 256>>>(edge_dst, n_edges);
    int nchunks = (n + 2047) / 2048;
    scan1_kernel<<<nchunks, 256>>>(n);
    scan2_kernel<<<1, 128>>>(nchunks);
    scan3_kernel<<<(n + 255) / 256, 256>>>(n);
    fill_kernel<<<(n_edges + 255) / 256, 256>>>(edge_src, edge_dst, edge_w,
                                                n_edges);

    // Fused layers (ping-pong ego buffers)
    float *eA = nullptr, *eB = nullptr;
    cudaGetSymbolAddress((void**)&eA, g_ego);
    cudaGetSymbolAddress((void**)&eB, g_ego2);
    float* cur = eA; float* nxt = eB;
    for (int k = 0; k < layers; k++) {
        layer_kernel<<<888, 256>>>(W_gc + (long long)k * EMB * EMB,
                                   b_gc + (long long)k * EMB,
                                   W_bi + (long long)k * EMB * EMB,
                                   b_bi + (long long)k * EMB,
                                   cur, nxt, n, EMB * (k + 1));
        float* t = cur; cur = nxt; nxt = t;
    }

    // Output gathers
    detect_kernel<<<1, 256>>>((const int*)users, nb);
    {
        long long total = 3LL * nb * 64;
        gather_kernel<<<(int)((total + 255) / 256), 256>>>(
            users, pos, neg, (float*)d_out, n_user, nb);
    }
}

// round 7
// speedup vs baseline: 2.0372x; 1.4470x over previous
#include <cuda_runtime.h>
#include <cuda_bf16.h>

#define EMB 64
#define N_USER_MAX 100000
#define N_ITEM_MAX 50000
#define NMAX (N_USER_MAX + N_ITEM_MAX)
#define EMAX 4200000          // max directed edges (2*N_INTER + slack)

typedef unsigned long long u64;

// -------------------- device scratch (allocation-free rule) ----------------
__device__ float g_ego [(size_t)NMAX * EMB];         // ping
__device__ float g_ego2[(size_t)NMAX * EMB];         // pong
__device__ float g_alle[(size_t)NMAX * EMB * 4];     // layer-concat output
__device__ int   g_deg [NMAX];
__device__ int   g_off [NMAX];                       // per-chunk-local excl scan
__device__ int   g_cur [NMAX];
__device__ int   g_bsum[128];                        // chunk base offsets
__device__ int2  g_csr [EMAX];                       // {src, weight-bits}
__device__ int   g_idx64;

// packed fp32x2 helpers (Blackwell)
__device__ __forceinline__ u64 splat2(float x) {
    u64 r;
    asm("mov.b64 %0, {%1,%1};" : "=l"(r) : "f"(x));
    return r;
}
__device__ __forceinline__ void fma2(u64& d, u64 a, u64 b) {
    asm("fma.rn.f32x2 %0, %1, %2, %3;" : "=l"(d) : "l"(a), "l"(b), "l"(d));
}
__device__ __forceinline__ float2 upk2(u64 v) {
    float2 r;
    asm("mov.b64 {%0,%1}, %2;" : "=f"(r.x), "=f"(r.y) : "l"(v));
    return r;
}

// ---------------------------------------------------------------------------
// Init: ego = concat(user_emb, item_emb); all_e[:,0:64] = ego; deg=cur=0
// ---------------------------------------------------------------------------
__global__ void init_kernel(const float4* __restrict__ ue,
                            const float4* __restrict__ ie,
                            int n_user, int n) {
    long long gid = (long long)blockIdx.x * blockDim.x + threadIdx.x;
    long long total = (long long)n * 16;
    if (gid >= total) return;
    if (gid < n) { g_deg[gid] = 0; g_cur[gid] = 0; }
    int node = (int)(gid >> 4);
    int c    = (int)(gid & 15);
    float4 v = (node < n_user) ? ue[(long long)node * 16 + c]
                               : ie[(long long)(node - n_user) * 16 + c];
    ((float4*)g_ego)[gid] = v;
    ((float4*)g_alle)[(long long)node * 64 + c] = v;   // cols 0..63
}

// -------------------------- CSR build --------------------------------------
__global__ void hist_kernel(const int* __restrict__ dst, int ne) {
    int e = blockIdx.x * blockDim.x + threadIdx.x;
    if (e < ne) atomicAdd(&g_deg[dst[e]], 1);
}

// per-2048-chunk exclusive scan of g_deg -> g_off, chunk totals -> g_bsum
__global__ __launch_bounds__(256) void scan1_kernel(int n) {
    __shared__ int sth[256];
    int tid = threadIdx.x;
    int base = blockIdx.x * 2048 + tid * 8;
    int v[8]; int sum = 0;
#pragma unroll
    for (int j = 0; j < 8; j++) {
        v[j] = (base + j < n) ? g_deg[base + j] : 0;
        sum += v[j];
    }
    sth[tid] = sum;
    __syncthreads();
    for (int o = 1; o < 256; o <<= 1) {
        int t = (tid >= o) ? sth[tid - o] : 0;
        __syncthreads();
        sth[tid] += t;
        __syncthreads();
    }
    int run = (tid > 0) ? sth[tid - 1] : 0;
#pragma unroll
    for (int j = 0; j < 8; j++) {
        if (base + j < n) g_off[base + j] = run;
        run += v[j];
    }
    if (tid == 255) g_bsum[blockIdx.x] = sth[255];
}

// exclusive scan of chunk totals (nchunks <= 128), one block
__global__ void scan2_kernel(int nb) {
    __shared__ int s[128];
    int tid = threadIdx.x;
    s[tid] = (tid < nb) ? g_bsum[tid] : 0;
    __syncthreads();
    for (int o = 1; o < 128; o <<= 1) {
        int t = (tid >= o) ? s[tid - o] : 0;
        __syncthreads();
        s[tid] += t;
        __syncthreads();
    }
    if (tid < nb) g_bsum[tid] = (tid > 0) ? s[tid - 1] : 0;
}

// fill CSR (offset = local scan + chunk base, computed on the fly)
__global__ void fill_kernel(const int* __restrict__ src,
                            const int* __restrict__ dst,
                            const float* __restrict__ w, int ne) {
    int e = blockIdx.x * blockDim.x + threadIdx.x;
    if (e >= ne) return;
    int d = dst[e];
    int pos = g_off[d] + g_bsum[d >> 11] + atomicAdd(&g_cur[d], 1);
    if (pos < EMAX)
        g_csr[pos] = make_int2(src[e], __float_as_int(w[e]));
}

// ---------------------------------------------------------------------------
// Fused layer: warp handles 4 nodes.
//   Phase 1 (per node): pull-aggregate side into regs, stage side & ego*side
//                       transposed into per-warp smem.
//   Phase 2 (quad):     dual GEMV, W element read once per 4 nodes,
//                       broadcast LDS for x, f32x2 FMAs, zero shuffles.
//   Phase 3 (per node): leaky_relu, L2 norm (5 shfl), store ego_out + alle.
// ---------------------------------------------------------------------------
__global__ __launch_bounds__(256, 4) void layer_kernel(
        const float* __restrict__ Wg, const float* __restrict__ bg,
        const float* __restrict__ Wb, const float* __restrict__ bb,
        const float* __restrict__ ego_in, float* __restrict__ ego_out,
        int n, int koff) {
    __shared__ float sWg[EMB * EMB];
    __shared__ float sWb[EMB * EMB];
    __shared__ float sbg[EMB], sbb[EMB];
    __shared__ float sxs[8][EMB][4];    // side, transposed per warp
    __shared__ float sxb[8][EMB][4];    // ego*side, transposed per warp

    int tid = threadIdx.x;
    for (int i = tid; i < EMB * EMB; i += 256) { sWg[i] = Wg[i]; sWb[i] = Wb[i]; }
    if (tid < EMB) { sbg[tid] = bg[tid]; sbb[tid] = bb[tid]; }
    __syncthreads();

    int warp = tid >> 5;
    int lane = tid & 31;
    const unsigned FULL = 0xFFFFFFFFu;
    const float2* ego2 = (const float2*)ego_in;

    int qbase = (blockIdx.x * 8 + warp) * 4;
    if (qbase >= n) return;

    // ---- Phase 1: aggregate 4 nodes ----
#pragma unroll
    for (int nd = 0; nd < 4; nd++) {
        int node = qbase + nd;
        float2 side = make_float2(0.f, 0.f);
        float2 eg   = make_float2(0.f, 0.f);
        if (node < n) {
            int beg     = g_off[node] + g_bsum[node >> 11];
            int cnt_all = g_deg[node];
            float2 a0 = {0.f,0.f}, a1 = {0.f,0.f}, a2 = {0.f,0.f}, a3 = {0.f,0.f};
            for (int base = 0; base < cnt_all; base += 32) {
                int2 ed = make_int2(0, 0);
                if (base + lane < cnt_all) ed = g_csr[beg + base + lane];
                int cnt = min(32, cnt_all - base);
                int k = 0;
                for (; k + 4 <= cnt; k += 4) {
                    int s0 = __shfl_sync(FULL, ed.x, k);
                    int s1 = __shfl_sync(FULL, ed.x, k + 1);
                    int s2 = __shfl_sync(FULL, ed.x, k + 2);
                    int s3 = __shfl_sync(FULL, ed.x, k + 3);
                    float w0 = __int_as_float(__shfl_sync(FULL, ed.y, k));
                    float w1 = __int_as_float(__shfl_sync(FULL, ed.y, k + 1));
                    float w2 = __int_as_float(__shfl_sync(FULL, ed.y, k + 2));
                    float w3 = __int_as_float(__shfl_sync(FULL, ed.y, k + 3));
                    float2 v0 = ego2[s0 * 32 + lane];
                    float2 v1 = ego2[s1 * 32 + lane];
                    float2 v2 = ego2[s2 * 32 + lane];
                    float2 v3 = ego2[s3 * 32 + lane];
                    a0.x = fmaf(w0, v0.x, a0.x); a0.y = fmaf(w0, v0.y, a0.y);
                    a1.x = fmaf(w1, v1.x, a1.x); a1.y = fmaf(w1, v1.y, a1.y);
                    a2.x = fmaf(w2, v2.x, a2.x); a2.y = fmaf(w2, v2.y, a2.y);
                    a3.x = fmaf(w3, v3.x, a3.x); a3.y = fmaf(w3, v3.y, a3.y);
                }
                for (; k < cnt; k++) {
                    int   ss = __shfl_sync(FULL, ed.x, k);
                    float ww = __int_as_float(__shfl_sync(FULL, ed.y, k));
                    float2 v = ego2[ss * 32 + lane];
                    a0.x = fmaf(ww, v.x, a0.x); a0.y = fmaf(ww, v.y, a0.y);
                }
            }
            side.x = (a0.x + a1.x) + (a2.x + a3.x);
            side.y = (a0.y + a1.y) + (a2.y + a3.y);
            eg = ego2[node * 32 + lane];
        }
        sxs[warp][2 * lane    ][nd] = side.x;
        sxs[warp][2 * lane + 1][nd] = side.y;
        sxb[warp][2 * lane    ][nd] = eg.x * side.x;
        sxb[warp][2 * lane + 1][nd] = eg.y * side.y;
    }
    __syncwarp();

    // ---- Phase 2: quad dual-GEMV ----
    u64 bgv = *(const u64*)&sbg[2 * lane];
    u64 bbv = *(const u64*)&sbb[2 * lane];
    u64 accg[4], accb[4];
#pragma unroll
    for (int nd = 0; nd < 4; nd++) { accg[nd] = bgv; accb[nd] = bbv; }

#pragma unroll 8
    for (int i = 0; i < EMB; i++) {
        float4 xs = *(const float4*)&sxs[warp][i][0];   // broadcast
        float4 xb = *(const float4*)&sxb[warp][i][0];   // broadcast
        u64 wg = *(const u64*)&sWg[i * EMB + 2 * lane];
        u64 wb = *(const u64*)&sWb[i * EMB + 2 * lane];
        fma2(accg[0], splat2(xs.x), wg);
        fma2(accg[1], splat2(xs.y), wg);
        fma2(accg[2], splat2(xs.z), wg);
        fma2(accg[3], splat2(xs.w), wg);
        fma2(accb[0], splat2(xb.x), wb);
        fma2(accb[1], splat2(xb.y), wb);
        fma2(accb[2], splat2(xb.z), wb);
        fma2(accb[3], splat2(xb.w), wb);
    }

    // ---- Phase 3: activation + norm + store ----
#pragma unroll
    for (int nd = 0; nd < 4; nd++) {
        int node = qbase + nd;
        float2 rg = upk2(accg[nd]);
        float2 rb = upk2(accb[nd]);
        float2 e2;
        e2.x = rg.x + rb.x;
        e2.y = rg.y + rb.y;
        e2.x = (e2.x >= 0.f) ? e2.x : 0.2f * e2.x;
        e2.y = (e2.y >= 0.f) ? e2.y : 0.2f * e2.y;
        float ssq = e2.x * e2.x + e2.y * e2.y;
#pragma unroll
        for (int o = 16; o > 0; o >>= 1) ssq += __shfl_xor_sync(FULL, ssq, o);
        float inv = 1.f / fmaxf(sqrtf(ssq), 1e-12f);
        if (node < n) {
            ((float2*)ego_out)[node * 32 + lane] = e2;
            *(float2*)&g_alle[(long long)node * 256 + koff + 2 * lane] =
                make_float2(e2.x * inv, e2.y * inv);
        }
    }
}

// ---------------------------------------------------------------------------
// int64 vs int32 index detection (odd 32-bit words all zero => int64 LE)
// ---------------------------------------------------------------------------
__global__ void detect_kernel(const int* __restrict__ users, int nb) {
    __shared__ int s;
    if (threadIdx.x == 0) s = 0;
    __syncthreads();
    int acc = 0;
    for (int i = threadIdx.x; i < nb / 2; i += blockDim.x)
        acc |= users[2 * i + 1];
    atomicOr(&s, acc);
    __syncthreads();
    if (threadIdx.x == 0) g_idx64 = (s == 0) ? 1 : 0;
}

// ---------------------------------------------------------------------------
// Gather final outputs: [u_g ; i_g[pos] ; i_g[neg]], each (nb, 256) fp32
// ---------------------------------------------------------------------------
__global__ void gather_kernel(const void* __restrict__ users,
                              const void* __restrict__ pos,
                              const void* __restrict__ neg,
                              float* __restrict__ out,
                              int n_user, int nb) {
    int flag = g_idx64;
    long long gid = (long long)blockIdx.x * blockDim.x + threadIdx.x;
    long long total = 3LL * nb * 64;
    if (gid >= total) return;
    int c = (int)(gid & 63);
    long long r = gid >> 6;
    int which = (int)(r / nb);
    int b     = (int)(r % nb);
    const void* p = (which == 0) ? users : (which == 1) ? pos : neg;
    long long idx = flag ? ((const long long*)p)[b]
                         : (long long)((const int*)p)[b];
    long long row = (which == 0) ? idx : ((long long)n_user + idx);
    ((float4*)out)[gid] = ((const float4*)g_alle)[row * 64 + c];
}

// ---------------------------------------------------------------------------
extern "C" void kernel_launch(void* const* d_in, const int* in_sizes, int n_in,
                              void* d_out, int out_size) {
    const float* user_emb = (const float*)d_in[0];
    const float* item_emb = (const float*)d_in[1];
    const float* W_gc     = (const float*)d_in[2];
    const float* b_gc     = (const float*)d_in[3];
    const float* W_bi     = (const float*)d_in[4];
    const float* b_bi     = (const float*)d_in[5];
    const float* edge_w   = (const float*)d_in[6];
    const int*   edge_src = (const int*)d_in[7];
    const int*   edge_dst = (const int*)d_in[8];
    const void*  users    = d_in[9];
    const void*  pos      = d_in[10];
    const void*  neg      = d_in[11];

    int n_user  = in_sizes[0] / EMB;
    int n_item  = in_sizes[1] / EMB;
    int n       = n_user + n_item;
    int n_edges = in_sizes[6];
    int layers  = in_sizes[2] / (EMB * EMB);
    int nb      = in_sizes[9];

    // (0) ego init + alle cols + deg/cur zero
    {
        long long total = (long long)n * 16;
        init_kernel<<<(int)((total + 255) / 256), 256>>>(
            (const float4*)user_emb, (const float4*)item_emb, n_user, n);
    }

    // (1-4) CSR build by dst
    hist_kernel<<<(n_edges + 255) / 256, 256>>>(edge_dst, n_edges);
    int nchunks = (n + 2047) / 2048;
    scan1_kernel<<<nchunks, 256>>>(n);
    scan2_kernel<<<1, 128>>>(nchunks);
    fill_kernel<<<(n_edges + 255) / 256, 256>>>(edge_src, edge_dst, edge_w,
                                                n_edges);

    // (5-7) fused layers, ping-pong ego
    float *eA = nullptr, *eB = nullptr;
    cudaGetSymbolAddress((void**)&eA, g_ego);
    cudaGetSymbolAddress((void**)&eB, g_ego2);
    float* cur = eA; float* nxt = eB;
    int lblocks = (n + 31) / 32;             // 1 warp per 4 nodes
    for (int k = 0; k < layers; k++) {
        layer_kernel<<<lblocks, 256>>>(W_gc + (long long)k * EMB * EMB,
                                       b_gc + (long long)k * EMB,
                                       W_bi + (long long)k * EMB * EMB,
                                       b_bi + (long long)k * EMB,
                                       cur, nxt, n, EMB * (k + 1));
        float* t = cur; cur = nxt; nxt = t;
    }

    // (8-9) output gathers
    detect_kernel<<<1, 256>>>((const int*)users, nb);
    {
        long long total = 3LL * nb * 64;
        gather_kernel<<<(int)((total + 255) / 256), 256>>>(
            users, pos, neg, (float*)d_out, n_user, nb);
    }
}

// round 8
// speedup vs baseline: 2.0466x; 1.0046x over previous
#include <cuda_runtime.h>
#include <cuda_bf16.h>

#define EMB 64
#define N_USER_MAX 100000
#define N_ITEM_MAX 50000
#define NMAX (N_USER_MAX + N_ITEM_MAX)
#define EMAX 4200000          // max directed edges (2*N_INTER + slack)

typedef unsigned long long u64;

// -------------------- device scratch (allocation-free rule) ----------------
__device__ float g_ego [(size_t)NMAX * EMB];         // ping
__device__ float g_ego2[(size_t)NMAX * EMB];         // pong
__device__ float g_alle[(size_t)NMAX * EMB * 4];     // layer-concat output
__device__ int   g_deg [NMAX];
__device__ int   g_off [NMAX];                       // per-chunk-local excl scan
__device__ int   g_cur [NMAX];
__device__ int   g_bsum[128];                        // chunk base offsets
__device__ int2  g_csr [EMAX];                       // {src, weight-bits}
__device__ int   g_idx64;

// packed fp32x2 helpers (Blackwell)
__device__ __forceinline__ u64 splat2(float x) {
    u64 r;
    asm("mov.b64 %0, {%1,%1};" : "=l"(r) : "f"(x));
    return r;
}
__device__ __forceinline__ void fma2(u64& d, u64 a, u64 b) {
    asm("fma.rn.f32x2 %0, %1, %2, %3;" : "=l"(d) : "l"(a), "l"(b), "l"(d));
}
__device__ __forceinline__ float2 upk2(u64 v) {
    float2 r;
    asm("mov.b64 {%0,%1}, %2;" : "=f"(r.x), "=f"(r.y) : "l"(v));
    return r;
}

// ---------------------------------------------------------------------------
// Init: ego = concat(user_emb, item_emb); all_e[:,0:64] = ego; deg=cur=0
// ---------------------------------------------------------------------------
__global__ void init_kernel(const float4* __restrict__ ue,
                            const float4* __restrict__ ie,
                            int n_user, int n) {
    long long gid = (long long)blockIdx.x * blockDim.x + threadIdx.x;
    long long total = (long long)n * 16;
    if (gid >= total) return;
    if (gid < n) { g_deg[gid] = 0; g_cur[gid] = 0; }
    int node = (int)(gid >> 4);
    int c    = (int)(gid & 15);
    float4 v = (node < n_user) ? ue[(long long)node * 16 + c]
                               : ie[(long long)(node - n_user) * 16 + c];
    ((float4*)g_ego)[gid] = v;
    ((float4*)g_alle)[(long long)node * 64 + c] = v;   // cols 0..63
}

// -------------------------- CSR build --------------------------------------
__global__ void hist_kernel(const int* __restrict__ dst, int ne) {
    int e = blockIdx.x * blockDim.x + threadIdx.x;
    if (e < ne) atomicAdd(&g_deg[dst[e]], 1);
}

// per-2048-chunk exclusive scan of g_deg -> g_off, chunk totals -> g_bsum
__global__ __launch_bounds__(256) void scan1_kernel(int n) {
    __shared__ int sth[256];
    int tid = threadIdx.x;
    int base = blockIdx.x * 2048 + tid * 8;
    int v[8]; int sum = 0;
#pragma unroll
    for (int j = 0; j < 8; j++) {
        v[j] = (base + j < n) ? g_deg[base + j] : 0;
        sum += v[j];
    }
    sth[tid] = sum;
    __syncthreads();
    for (int o = 1; o < 256; o <<= 1) {
        int t = (tid >= o) ? sth[tid - o] : 0;
        __syncthreads();
        sth[tid] += t;
        __syncthreads();
    }
    int run = (tid > 0) ? sth[tid - 1] : 0;
#pragma unroll
    for (int j = 0; j < 8; j++) {
        if (base + j < n) g_off[base + j] = run;
        run += v[j];
    }
    if (tid == 255) g_bsum[blockIdx.x] = sth[255];
}

// exclusive scan of chunk totals (nchunks <= 128), one block
__global__ void scan2_kernel(int nb) {
    __shared__ int s[128];
    int tid = threadIdx.x;
    s[tid] = (tid < nb) ? g_bsum[tid] : 0;
    __syncthreads();
    for (int o = 1; o < 128; o <<= 1) {
        int t = (tid >= o) ? s[tid - o] : 0;
        __syncthreads();
        s[tid] += t;
        __syncthreads();
    }
    if (tid < nb) g_bsum[tid] = (tid > 0) ? s[tid - 1] : 0;
}

// fill CSR (offset = local scan + chunk base, computed on the fly)
__global__ void fill_kernel(const int* __restrict__ src,
                            const int* __restrict__ dst,
                            const float* __restrict__ w, int ne) {
    int e = blockIdx.x * blockDim.x + threadIdx.x;
    if (e >= ne) return;
    int d = dst[e];
    int pos = g_off[d] + g_bsum[d >> 11] + atomicAdd(&g_cur[d], 1);
    if (pos < EMAX)
        g_csr[pos] = make_int2(src[e], __float_as_int(w[e]));
}

// ---------------------------------------------------------------------------
// Fused layer: warp handles 4 nodes.
//   Phase 1 (per node): pull-aggregate side (depth-8 MLP, L1-bypass gathers),
//                       stage side & ego*side transposed into per-warp smem.
//   Phase 2 (quad):     dual GEMV, W element read once per 4 nodes,
//                       broadcast LDS for x, f32x2 FMAs, zero shuffles.
//   Phase 3 (per node): leaky_relu, L2 norm (5 shfl), store ego_out + alle.
// ---------------------------------------------------------------------------
__global__ __launch_bounds__(256, 4) void layer_kernel(
        const float* __restrict__ Wg, const float* __restrict__ bg,
        const float* __restrict__ Wb, const float* __restrict__ bb,
        const float* __restrict__ ego_in, float* __restrict__ ego_out,
        int n, int koff) {
    __shared__ float sWg[EMB * EMB];
    __shared__ float sWb[EMB * EMB];
    __shared__ float sbg[EMB], sbb[EMB];
    __shared__ float sxs[8][EMB][4];    // side, transposed per warp
    __shared__ float sxb[8][EMB][4];    // ego*side, transposed per warp

    int tid = threadIdx.x;
    for (int i = tid; i < EMB * EMB; i += 256) { sWg[i] = Wg[i]; sWb[i] = Wb[i]; }
    if (tid < EMB) { sbg[tid] = bg[tid]; sbb[tid] = bb[tid]; }
    __syncthreads();

    int warp = tid >> 5;
    int lane = tid & 31;
    const unsigned FULL = 0xFFFFFFFFu;
    const float2* ego2 = (const float2*)ego_in;

    int qbase = (blockIdx.x * 8 + warp) * 4;
    if (qbase >= n) return;

    // ---- Phase 1: aggregate 4 nodes ----
#pragma unroll
    for (int nd = 0; nd < 4; nd++) {
        int node = qbase + nd;
        float2 side = make_float2(0.f, 0.f);
        float2 eg   = make_float2(0.f, 0.f);
        if (node < n) {
            int beg     = g_off[node] + g_bsum[node >> 11];
            int cnt_all = g_deg[node];
            float2 a0 = {0.f,0.f}, a1 = {0.f,0.f}, a2 = {0.f,0.f}, a3 = {0.f,0.f};
            for (int base = 0; base < cnt_all; base += 32) {
                int2 ed = make_int2(0, 0);
                if (base + lane < cnt_all) ed = g_csr[beg + base + lane];
                int cnt = min(32, cnt_all - base);
                int k = 0;
                // depth-8: all broadcasts + all gathers issued before FMAs
                for (; k + 8 <= cnt; k += 8) {
                    float2 v[8]; float w[8];
#pragma unroll
                    for (int j = 0; j < 8; j++) {
                        int s = __shfl_sync(FULL, ed.x, k + j);
                        w[j]  = __int_as_float(__shfl_sync(FULL, ed.y, k + j));
                        v[j]  = __ldcg(ego2 + s * 32 + lane);
                    }
#pragma unroll
                    for (int j = 0; j < 8; j++) {
                        float2* a = (j & 2) ? ((j & 1) ? &a3 : &a2)
                                            : ((j & 1) ? &a1 : &a0);
                        a->x = fmaf(w[j], v[j].x, a->x);
                        a->y = fmaf(w[j], v[j].y, a->y);
                    }
                }
                for (; k + 4 <= cnt; k += 4) {
                    float2 v[4]; float w[4];
#pragma unroll
                    for (int j = 0; j < 4; j++) {
                        int s = __shfl_sync(FULL, ed.x, k + j);
                        w[j]  = __int_as_float(__shfl_sync(FULL, ed.y, k + j));
                        v[j]  = __ldcg(ego2 + s * 32 + lane);
                    }
                    a0.x = fmaf(w[0], v[0].x, a0.x); a0.y = fmaf(w[0], v[0].y, a0.y);
                    a1.x = fmaf(w[1], v[1].x, a1.x); a1.y = fmaf(w[1], v[1].y, a1.y);
                    a2.x = fmaf(w[2], v[2].x, a2.x); a2.y = fmaf(w[2], v[2].y, a2.y);
                    a3.x = fmaf(w[3], v[3].x, a3.x); a3.y = fmaf(w[3], v[3].y, a3.y);
                }
                for (; k < cnt; k++) {
                    int   ss = __shfl_sync(FULL, ed.x, k);
                    float ww = __int_as_float(__shfl_sync(FULL, ed.y, k));
                    float2 v = __ldcg(ego2 + ss * 32 + lane);
                    a0.x = fmaf(ww, v.x, a0.x); a0.y = fmaf(ww, v.y, a0.y);
                }
            }
            side.x = (a0.x + a1.x) + (a2.x + a3.x);
            side.y = (a0.y + a1.y) + (a2.y + a3.y);
            eg = ego2[node * 32 + lane];
        }
        sxs[warp][2 * lane    ][nd] = side.x;
        sxs[warp][2 * lane + 1][nd] = side.y;
        sxb[warp][2 * lane    ][nd] = eg.x * side.x;
        sxb[warp][2 * lane + 1][nd] = eg.y * side.y;
    }
    __syncwarp();

    // ---- Phase 2: quad dual-GEMV ----
    u64 bgv = *(const u64*)&sbg[2 * lane];
    u64 bbv = *(const u64*)&sbb[2 * lane];
    u64 accg[4], accb[4];
#pragma unroll
    for (int nd = 0; nd < 4; nd++) { accg[nd] = bgv; accb[nd] = bbv; }

#pragma unroll 8
    for (int i = 0; i < EMB; i++) {
        float4 xs = *(const float4*)&sxs[warp][i][0];   // broadcast
        float4 xb = *(const float4*)&sxb[warp][i][0];   // broadcast
        u64 wg = *(const u64*)&sWg[i * EMB + 2 * lane];
        u64 wb = *(const u64*)&sWb[i * EMB + 2 * lane];
        fma2(accg[0], splat2(xs.x), wg);
        fma2(accg[1], splat2(xs.y), wg);
        fma2(accg[2], splat2(xs.z), wg);
        fma2(accg[3], splat2(xs.w), wg);
        fma2(accb[0], splat2(xb.x), wb);
        fma2(accb[1], splat2(xb.y), wb);
        fma2(accb[2], splat2(xb.z), wb);
        fma2(accb[3], splat2(xb.w), wb);
    }

    // ---- Phase 3: activation + norm + store ----
#pragma unroll
    for (int nd = 0; nd < 4; nd++) {
        int node = qbase + nd;
        float2 rg = upk2(accg[nd]);
        float2 rb = upk2(accb[nd]);
        float2 e2;
        e2.x = rg.x + rb.x;
        e2.y = rg.y + rb.y;
        e2.x = (e2.x >= 0.f) ? e2.x : 0.2f * e2.x;
        e2.y = (e2.y >= 0.f) ? e2.y : 0.2f * e2.y;
        float ssq = e2.x * e2.x + e2.y * e2.y;
#pragma unroll
        for (int o = 16; o > 0; o >>= 1) ssq += __shfl_xor_sync(FULL, ssq, o);
        float inv = 1.f / fmaxf(sqrtf(ssq), 1e-12f);
        if (node < n) {
            ((float2*)ego_out)[node * 32 + lane] = e2;
            *(float2*)&g_alle[(long long)node * 256 + koff + 2 * lane] =
                make_float2(e2.x * inv, e2.y * inv);
        }
    }
}

// ---------------------------------------------------------------------------
// int64 vs int32 index detection (odd 32-bit words all zero => int64 LE)
// ---------------------------------------------------------------------------
__global__ void detect_kernel(const int* __restrict__ users, int nb) {
    __shared__ int s;
    if (threadIdx.x == 0) s = 0;
    __syncthreads();
    int acc = 0;
    for (int i = threadIdx.x; i < nb / 2; i += blockDim.x)
        acc |= users[2 * i + 1];
    atomicOr(&s, acc);
    __syncthreads();
    if (threadIdx.x == 0) g_idx64 = (s == 0) ? 1 : 0;
}

// ---------------------------------------------------------------------------
// Gather final outputs: [u_g ; i_g[pos] ; i_g[neg]], each (nb, 256) fp32
// ---------------------------------------------------------------------------
__global__ void gather_kernel(const void* __restrict__ users,
                              const void* __restrict__ pos,
                              const void* __restrict__ neg,
                              float* __restrict__ out,
                              int n_user, int nb) {
    int flag = g_idx64;
    long long gid = (long long)blockIdx.x * blockDim.x + threadIdx.x;
    long long total = 3LL * nb * 64;
    if (gid >= total) return;
    int c = (int)(gid & 63);
    long long r = gid >> 6;
    int which = (int)(r / nb);
    int b     = (int)(r % nb);
    const void* p = (which == 0) ? users : (which == 1) ? pos : neg;
    long long idx = flag ? ((const long long*)p)[b]
                         : (long long)((const int*)p)[b];
    long long row = (which == 0) ? idx : ((long long)n_user + idx);
    ((float4*)out)[gid] = ((const float4*)g_alle)[row * 64 + c];
}

// ---------------------------------------------------------------------------
extern "C" void kernel_launch(void* const* d_in, const int* in_sizes, int n_in,
                              void* d_out, int out_size) {
    const float* user_emb = (const float*)d_in[0];
    const float* item_emb = (const float*)d_in[1];
    const float* W_gc     = (const float*)d_in[2];
    const float* b_gc     = (const float*)d_in[3];
    const float* W_bi     = (const float*)d_in[4];
    const float* b_bi     = (const float*)d_in[5];
    const float* edge_w   = (const float*)d_in[6];
    const int*   edge_src = (const int*)d_in[7];
    const int*   edge_dst = (const int*)d_in[8];
    const void*  users    = d_in[9];
    const void*  pos      = d_in[10];
    const void*  neg      = d_in[11];

    int n_user  = in_sizes[0] / EMB;
    int n_item  = in_sizes[1] / EMB;
    int n       = n_user + n_item;
    int n_edges = in_sizes[6];
    int layers  = in_sizes[2] / (EMB * EMB);
    int nb      = in_sizes[9];

    // (0) ego init + alle cols + deg/cur zero
    {
        long long total = (long long)n * 16;
        init_kernel<<<(int)((total + 255) / 256), 256>>>(
            (const float4*)user_emb, (const float4*)item_emb, n_user, n);
    }

    // (1-4) CSR build by dst
    hist_kernel<<<(n_edges + 255) / 256, 256>>>(edge_dst, n_edges);
    int nchunks = (n + 2047) / 2048;
    scan1_kernel<<<nchunks, 256>>>(n);
    scan2_kernel<<<1, 128>>>(nchunks);
    fill_kernel<<<(n_edges + 255) / 256, 256>>>(edge_src, edge_dst, edge_w,
                                                n_edges);

    // (5-7) fused layers, ping-pong ego
    float *eA = nullptr, *eB = nullptr;
    cudaGetSymbolAddress((void**)&eA, g_ego);
    cudaGetSymbolAddress((void**)&eB, g_ego2);
    float* cur = eA; float* nxt = eB;
    int lblocks = (n + 31) / 32;             // 1 warp per 4 nodes
    for (int k = 0; k < layers; k++) {
        layer_kernel<<<lblocks, 256>>>(W_gc + (long long)k * EMB * EMB,
                                       b_gc + (long long)k * EMB,
                                       W_bi + (long long)k * EMB * EMB,
                                       b_bi + (long long)k * EMB,
                                       cur, nxt, n, EMB * (k + 1));
        float* t = cur; cur = nxt; nxt = t;
    }

    // (8-9) output gathers
    detect_kernel<<<1, 256>>>((const int*)users, nb);
    {
        long long total = 3LL * nb * 64;
        gather_kernel<<<(int)((total + 255) / 256), 256>>>(
            users, pos, neg, (float*)d_out, n_user, nb);
    }
}